// round 8
// baseline (speedup 1.0000x reference)
#include <cuda_runtime.h>

#define NN 50000
#define EE 800000
#define HH 128
#define CUTOFF_V 10.0f

// ---------------- device scratch (no allocations allowed) ----------------
__device__ float g_W[(size_t)EE * HH];     // edge gate rows (only active rows valid)
__device__ float g_hA[NN * HH];
__device__ float g_hB[NN * HH];
__device__ float g_agg[NN * HH];
__device__ int g_active[EE];
__device__ unsigned char g_mask[EE];
__device__ int g_count;

// ---------------- f32x2 packed-FMA helpers (Blackwell) ----------------
__device__ __forceinline__ unsigned long long pk2(float lo, float hi) {
    unsigned long long r;
    asm("mov.b64 %0, {%1, %2};" : "=l"(r) : "f"(lo), "f"(hi));
    return r;
}
__device__ __forceinline__ void fma2(unsigned long long& d, unsigned long long a, unsigned long long b) {
    asm("fma.rn.f32x2 %0, %1, %2, %0;" : "+l"(d) : "l"(a), "l"(b));
}
__device__ __forceinline__ float2 up2(unsigned long long v) {
    float2 f;
    asm("mov.b64 {%0, %1}, %2;" : "=f"(f.x), "=f"(f.y) : "l"(v));
    return f;
}

// 64x128 @ 128x128 register-tiled GEMM from shared memory.
// Thread tile: 8 rows x 4 cols (2 packed f32x2 col-pairs). 256 threads = 8 rowgroups x 32 colgroups.
__device__ __forceinline__ void gemm128(const float* __restrict__ sA, const float* __restrict__ sW,
                                        int rg, int cg, unsigned long long acc[8][2]) {
    const float* a0 = sA + rg * (8 * 128);
    const float* w0 = sW + cg * 4;
#pragma unroll 4
    for (int k = 0; k < 128; ++k) {
        ulonglong2 b = *reinterpret_cast<const ulonglong2*>(w0 + k * 128);
#pragma unroll
        for (int i = 0; i < 8; ++i) {
            float a = a0[i * 128 + k];
            unsigned long long a2 = pk2(a, a);
            fma2(acc[i][0], a2, b.x);
            fma2(acc[i][1], a2, b.y);
        }
    }
}

// ---------------- small kernels ----------------
__global__ void k_init() { g_count = 0; }

// mask + warp-aggregated compaction of active edges (E divisible by 256)
__global__ void __launch_bounds__(256) k_compact(const float* __restrict__ elen) {
    int e = blockIdx.x * 256 + threadIdx.x;
    int lane = threadIdx.x & 31;
    bool a = (elen[e] <= CUTOFF_V);
    g_mask[e] = a ? (unsigned char)1 : (unsigned char)0;
    unsigned m = __ballot_sync(0xffffffffu, a);
    int cnt = __popc(m);
    int base = 0;
    if (lane == 0 && cnt) base = atomicAdd(&g_count, cnt);
    base = __shfl_sync(0xffffffffu, base, 0);
    if (a) {
        int off = __popc(m & ((1u << lane) - 1u));
        g_active[base + off] = e;
    }
}

__global__ void __launch_bounds__(256) k_zero_agg() {
    int i = blockIdx.x * 256 + threadIdx.x;  // exactly N*H/4 threads
    reinterpret_cast<float4*>(g_agg)[i] = make_float4(0.f, 0.f, 0.f, 0.f);
}

// message + scatter-add: one warp per edge, 4 floats per lane.
__global__ void __launch_bounds__(256) k_message(const int* __restrict__ ei,
                                                 const float* __restrict__ hin) {
    int idx = blockIdx.x * 256 + threadIdx.x;  // exactly E*32 threads
    int e = idx >> 5;
    int c4 = idx & 31;
    int s = __ldg(ei + e);
    float4 m = __ldg(reinterpret_cast<const float4*>(hin) + s * 32 + c4);
    if (g_mask[e]) {
        float4 wv = __ldcs(reinterpret_cast<const float4*>(g_W + (size_t)e * HH) + c4);
        m.x += wv.x; m.y += wv.y; m.z += wv.z; m.w += wv.w;
    }
    m.x = fmaxf(m.x, 0.f); m.y = fmaxf(m.y, 0.f);
    m.z = fmaxf(m.z, 0.f); m.w = fmaxf(m.w, 0.f);
    int d = __ldg(ei + EE + e);
    float* ap = g_agg + (size_t)d * HH + c4 * 4;
    asm volatile("red.global.add.v4.f32 [%0], {%1,%2,%3,%4};"
                 :: "l"(ap), "f"(m.x), "f"(m.y), "f"(m.z), "f"(m.w) : "memory");
}

// ---------------- fused 2-layer MLP (both weight mats in shared, exact fp32) ----------------
// MODE 0: edge gate  : rows = g_count (compacted), in = edge_attr[g_active[r]], out = g_W[e]
// MODE 1: node update: in = g_agg + hin, out = relu(mlp(in)) + hin
// MODE 2: node update: in = g_agg + hin, out = mlp(in) + hin   (last conv)
template <int MODE>
__global__ void __launch_bounds__(256, 1) k_mlp2(const float* __restrict__ inp,
                                                 const float* __restrict__ hin,
                                                 const float* __restrict__ wa,
                                                 const float* __restrict__ ba,
                                                 const float* __restrict__ wb,
                                                 const float* __restrict__ bb,
                                                 float* __restrict__ hout) {
    extern __shared__ float sm[];
    float* sWa = sm;            // 16384 floats
    float* sWb = sm + 16384;    // 16384
    float* sIn = sm + 32768;    // 8192
    float* sHid = sm + 40960;   // 8192   (total 192 KB)

    for (int i = threadIdx.x; i < 4096; i += 256) {
        reinterpret_cast<float4*>(sWa)[i] = reinterpret_cast<const float4*>(wa)[i];
        reinterpret_cast<float4*>(sWb)[i] = reinterpret_cast<const float4*>(wb)[i];
    }
    __syncthreads();  // weights visible to all threads before first gemm

    const int rows = (MODE == 0) ? g_count : NN;
    const int ntiles = (rows + 63) >> 6;
    const int rg = threadIdx.x >> 5, cg = threadIdx.x & 31;
    const float4 bav = reinterpret_cast<const float4*>(ba)[cg];
    const float4 bbv = reinterpret_cast<const float4*>(bb)[cg];

    for (int t = blockIdx.x; t < ntiles; t += gridDim.x) {
        const int base = t << 6;
        // load 64x128 input tile
        for (int i = threadIdx.x; i < 2048; i += 256) {
            int r = i >> 5, c4 = i & 31;
            int gr = base + r;
            float4 v = make_float4(0.f, 0.f, 0.f, 0.f);
            if (gr < rows) {
                if constexpr (MODE == 0) {
                    int e = g_active[gr];
                    v = __ldcs(reinterpret_cast<const float4*>(inp + (size_t)e * HH) + c4);
                } else {
                    float4 x = reinterpret_cast<const float4*>(g_agg)[gr * 32 + c4];
                    float4 y = __ldg(reinterpret_cast<const float4*>(hin) + gr * 32 + c4);
                    v = make_float4(x.x + y.x, x.y + y.y, x.z + y.z, x.w + y.w);
                }
            }
            reinterpret_cast<float4*>(sIn)[i] = v;
        }
        __syncthreads();  // S1: sIn ready (also guards prev-iter gemm2 sHid readers)

        unsigned long long acc[8][2];
#pragma unroll
        for (int i = 0; i < 8; ++i) { acc[i][0] = 0ULL; acc[i][1] = 0ULL; }
        gemm128(sIn, sWa, rg, cg, acc);
#pragma unroll
        for (int i = 0; i < 8; ++i) {
            float2 lo = up2(acc[i][0]), hi = up2(acc[i][1]);
            float4 v = make_float4(fmaxf(lo.x + bav.x, 0.f), fmaxf(lo.y + bav.y, 0.f),
                                   fmaxf(hi.x + bav.z, 0.f), fmaxf(hi.y + bav.w, 0.f));
            reinterpret_cast<float4*>(sHid + (rg * 8 + i) * 128)[cg] = v;
        }
        __syncthreads();  // S2: sHid ready (also guarantees all gemm1 sIn reads done)

#pragma unroll
        for (int i = 0; i < 8; ++i) { acc[i][0] = 0ULL; acc[i][1] = 0ULL; }
        gemm128(sHid, sWb, rg, cg, acc);
#pragma unroll
        for (int i = 0; i < 8; ++i) {
            int gr = base + rg * 8 + i;
            if (gr < rows) {
                float2 lo = up2(acc[i][0]), hi = up2(acc[i][1]);
                float4 v = make_float4(lo.x + bbv.x, lo.y + bbv.y, hi.x + bbv.z, hi.y + bbv.w);
                if constexpr (MODE == 0) {
                    int e = g_active[gr];
                    __stcs(reinterpret_cast<float4*>(g_W + (size_t)e * HH) + cg, v);
                } else {
                    if constexpr (MODE == 1) {
                        v.x = fmaxf(v.x, 0.f); v.y = fmaxf(v.y, 0.f);
                        v.z = fmaxf(v.z, 0.f); v.w = fmaxf(v.w, 0.f);
                    }
                    float4 hr = __ldg(reinterpret_cast<const float4*>(hin) + gr * 32 + cg);
                    v.x += hr.x; v.y += hr.y; v.z += hr.z; v.w += hr.w;
                    reinterpret_cast<float4*>(hout)[gr * 32 + cg] = v;
                }
            }
        }
        // next iteration's S1 provides the needed barrier before sIn/sHid reuse
    }
}

// ---------------- node embedding: x = relu(z@w0a+b0a)@w0b+b0b (K1=5) ----------------
__global__ void __launch_bounds__(256) k_node_emb(const float* __restrict__ z,
                                                  const float* __restrict__ w0a,
                                                  const float* __restrict__ b0a,
                                                  const float* __restrict__ w0b,
                                                  const float* __restrict__ b0b) {
    extern __shared__ float sm[];
    float* sWb = sm;            // 16384
    float* sHid = sm + 16384;   // 8192
    float* sWa = sm + 24576;    // 640
    for (int i = threadIdx.x; i < 4096; i += 256)
        reinterpret_cast<float4*>(sWb)[i] = reinterpret_cast<const float4*>(w0b)[i];
    for (int i = threadIdx.x; i < 640; i += 256) sWa[i] = w0a[i];
    __syncthreads();  // FIX: sWa fully written before tile-0 hidden computation reads it

    const int rg = threadIdx.x >> 5, cg = threadIdx.x & 31;
    const float4 bbv = reinterpret_cast<const float4*>(b0b)[cg];
    const int ntiles = (NN + 63) / 64;
    for (int t = blockIdx.x; t < ntiles; t += gridDim.x) {
        int base = t * 64;
        for (int i = threadIdx.x; i < 8192; i += 256) {
            int r = i >> 7, c = i & 127;
            int gr = base + r;
            float acc = 0.f;
            if (gr < NN) {
#pragma unroll
                for (int k = 0; k < 5; ++k)
                    acc = fmaf(__ldg(z + gr * 5 + k), sWa[k * 128 + c], acc);
                acc = fmaxf(acc + __ldg(b0a + c), 0.f);
            }
            sHid[i] = acc;
        }
        __syncthreads();
        unsigned long long acc[8][2];
#pragma unroll
        for (int i = 0; i < 8; ++i) { acc[i][0] = 0ULL; acc[i][1] = 0ULL; }
        gemm128(sHid, sWb, rg, cg, acc);
#pragma unroll
        for (int i = 0; i < 8; ++i) {
            int gr = base + rg * 8 + i;
            if (gr < NN) {
                float2 lo = up2(acc[i][0]), hi = up2(acc[i][1]);
                float4 v = make_float4(lo.x + bbv.x, lo.y + bbv.y, hi.x + bbv.z, hi.y + bbv.w);
                reinterpret_cast<float4*>(g_hA)[gr * 32 + cg] = v;
            }
        }
        __syncthreads();  // sHid reuse guard
    }
}

// ---------------- launch ----------------
extern "C" void kernel_launch(void* const* d_in, const int* in_sizes, int n_in,
                              void* d_out, int out_size) {
    const float* z    = (const float*)d_in[0];
    const int*   ei   = (const int*)d_in[1];
    const float* eatt = (const float*)d_in[2];
    const float* elen = (const float*)d_in[3];
    const float* w0a  = (const float*)d_in[4];
    const float* b0a  = (const float*)d_in[5];
    const float* w0b  = (const float*)d_in[6];
    const float* b0b  = (const float*)d_in[7];
    const float* w1a  = (const float*)d_in[8];
    const float* b1a  = (const float*)d_in[9];
    const float* w1b  = (const float*)d_in[10];
    const float* b1b  = (const float*)d_in[11];
    const float* w2a  = (const float*)d_in[12];
    const float* b2a  = (const float*)d_in[13];
    const float* w2b  = (const float*)d_in[14];
    const float* b2b  = (const float*)d_in[15];
    float* out = (float*)d_out;

    cudaFuncSetAttribute(k_mlp2<0>, cudaFuncAttributeMaxDynamicSharedMemorySize, 196608);
    cudaFuncSetAttribute(k_mlp2<1>, cudaFuncAttributeMaxDynamicSharedMemorySize, 196608);
    cudaFuncSetAttribute(k_mlp2<2>, cudaFuncAttributeMaxDynamicSharedMemorySize, 196608);
    cudaFuncSetAttribute(k_node_emb, cudaFuncAttributeMaxDynamicSharedMemorySize, 101376);

    float *hA, *hB;
    cudaGetSymbolAddress((void**)&hA, g_hA);
    cudaGetSymbolAddress((void**)&hB, g_hB);

    const int ZERO_BLOCKS = (NN * HH / 4) / 256;  // 6250
    const int MSG_BLOCKS  = (EE * 32) / 256;      // 100000

    k_init<<<1, 1>>>();
    k_compact<<<EE / 256, 256>>>(elen);
    k_node_emb<<<296, 256, 100864>>>(z, w0a, b0a, w0b, b0b);
    k_mlp2<0><<<148, 256, 196608>>>(eatt, nullptr, w2a, b2a, w2b, b2b, nullptr);

    // conv 0: hA -> hB
    k_zero_agg<<<ZERO_BLOCKS, 256>>>();
    k_message<<<MSG_BLOCKS, 256>>>(ei, hA);
    k_mlp2<1><<<148, 256, 196608>>>(nullptr, hA, w1a, b1a, w1b, b1b, hB);

    // conv 1: hB -> hA
    k_zero_agg<<<ZERO_BLOCKS, 256>>>();
    k_message<<<MSG_BLOCKS, 256>>>(ei, hB);
    k_mlp2<1><<<148, 256, 196608>>>(nullptr, hB, w1a, b1a, w1b, b1b, hA);

    // conv 2: hA -> out (no inter-layer relu)
    k_zero_agg<<<ZERO_BLOCKS, 256>>>();
    k_message<<<MSG_BLOCKS, 256>>>(ei, hA);
    k_mlp2<2><<<148, 256, 196608>>>(nullptr, hA, w1a, b1a, w1b, b1b, out);
}